// round 6
// baseline (speedup 1.0000x reference)
#include <cuda_runtime.h>
#include <cfloat>
#include <math.h>
#include <cstdint>
#include <mma.h>

using namespace nvcuda;

// Problem constants
#define NN   20000
#define NE   320000
#define HC   512
#define NH   4
#define OC   128
#define KDIM 512
#define NDIM 512

// -------- scratch (g_xl padded: last M-block stores rows up to 20095) ----
__device__ float g_xl[(size_t)(NN + 128) * HC];
__device__ float g_xc[(size_t)NN * KDIM];      // x, RN-rounded to tf32
__device__ float g_wc[(size_t)KDIM * NDIM];    // W, RN-rounded to tf32
__device__ float g_as[NN * NH];
__device__ float g_ad[NN * NH];
__device__ float g_amax[NN * NH];
__device__ float g_den[NN * NH];

// ---------------- init ----------------
__global__ void k_init(float* __restrict__ out) {
    int i = blockIdx.x * blockDim.x + threadIdx.x;
    if (i < NN * OC) out[i] = 0.f;
    if (i < NN * NH) { g_amax[i] = -FLT_MAX; g_den[i] = 0.f; }
}

// ---------------- tf32 RN pre-conversion of x and W ----------------
__device__ __forceinline__ float tf32rn(float f) {
    float r;
    asm("cvt.rna.tf32.f32 %0, %1;" : "=f"(r) : "f"(f));
    return r;
}
__global__ void k_cvt(const float* __restrict__ x, const float* __restrict__ W) {
    const int totx = NN * KDIM / 4;         // 2,560,000
    const int totw = KDIM * NDIM / 4;       //    65,536
    int i = blockIdx.x * blockDim.x + threadIdx.x;
    if (i < totx) {
        float4 v = ((const float4*)x)[i];
        v.x = tf32rn(v.x); v.y = tf32rn(v.y); v.z = tf32rn(v.z); v.w = tf32rn(v.w);
        ((float4*)g_xc)[i] = v;
    } else if (i < totx + totw) {
        int j = i - totx;
        float4 v = ((const float4*)W)[j];
        v.x = tf32rn(v.x); v.y = tf32rn(v.y); v.z = tf32rn(v.z); v.w = tf32rn(v.w);
        ((float4*)g_wc)[j] = v;
    }
}

// ---------------- GEMM: g_xl = g_xc @ g_wc (tf32 wmma, 128x128x32) -------
// 3-stage cp.async pipeline, single barrier per chunk. Operands are
// pre-rounded to tf32, so the HMMA's operand truncation is exact.
#define BLK_K  32
#define LDA_S  36      // 128 x 36 floats (padded)
#define LDB_S  136     // 32 x 136 floats (padded)
#define A_FLOATS (128 * LDA_S)
#define B_FLOATS (BLK_K * LDB_S)
#define STAGE_FLOATS (A_FLOATS + B_FLOATS)
#define NSTAGE 3
#define GEMM_SMEM (NSTAGE * STAGE_FLOATS * 4)

__device__ __forceinline__ uint32_t smem_u32(const void* p) {
    uint32_t a;
    asm("{ .reg .u64 t; cvta.to.shared.u64 t, %1; cvt.u32.u64 %0, t; }" : "=r"(a) : "l"(p));
    return a;
}

__global__ __launch_bounds__(256) void k_gemm_tc() {
    extern __shared__ float smem[];
    float* As = smem;                           // [NSTAGE][128][LDA_S]
    float* Bs = smem + NSTAGE * A_FLOATS;       // [NSTAGE][BLK_K][LDB_S]

    const int tid = threadIdx.x;
    const int warpId = tid >> 5;
    const int warpM = warpId & 3;         // 0..3 -> 32-row slab
    const int warpN = warpId >> 2;        // 0..1 -> 64-col slab
    const int m0 = blockIdx.y * 128;
    const int n0 = blockIdx.x * 128;

    const uint32_t sA = smem_u32(As);
    const uint32_t sB = smem_u32(Bs);

    auto load_stage = [&](int kc, int buf) {
        const int k0 = kc * BLK_K;
        #pragma unroll
        for (int it = 0; it < 4; it++) {
            int id = tid + it * 256;
            int r = id >> 3, q = id & 7;         // r: 0..127, q: 0..7 (16B seg)
            int grow = m0 + r;
            const float* gp = g_xc + (size_t)(grow < NN ? grow : 0) * KDIM + k0 + q * 4;
            int sz = (grow < NN) ? 16 : 0;
            uint32_t so = sA + (buf * A_FLOATS + r * LDA_S + q * 4) * 4;
            asm volatile("cp.async.cg.shared.global [%0], [%1], 16, %2;"
                         :: "r"(so), "l"(gp), "r"(sz));
        }
        #pragma unroll
        for (int it = 0; it < 4; it++) {
            int id = tid + it * 256;
            int r = id >> 5, q = id & 31;        // r: 0..31, q: 0..31
            const float* gp = g_wc + (size_t)(k0 + r) * NDIM + n0 + q * 4;
            uint32_t so = sB + (buf * B_FLOATS + r * LDB_S + q * 4) * 4;
            asm volatile("cp.async.cg.shared.global [%0], [%1], 16;"
                         :: "r"(so), "l"(gp));
        }
        asm volatile("cp.async.commit_group;" ::: "memory");
    };

    wmma::fragment<wmma::accumulator, 16, 16, 8, float> acc[2][4];
    #pragma unroll
    for (int i = 0; i < 2; i++)
        #pragma unroll
        for (int j = 0; j < 4; j++) wmma::fill_fragment(acc[i][j], 0.f);

    load_stage(0, 0);
    load_stage(1, 1);

    const int NCHUNK = KDIM / BLK_K;   // 16
    for (int kc = 0; kc < NCHUNK; kc++) {
        const int buf = kc % NSTAGE;
        if (kc + 1 < NCHUNK)
            asm volatile("cp.async.wait_group 1;" ::: "memory");
        else
            asm volatile("cp.async.wait_group 0;" ::: "memory");
        // one barrier: cp.async visibility + WAR safety for buffer (kc+2)%3
        __syncthreads();
        if (kc + 2 < NCHUNK) load_stage(kc + 2, (kc + 2) % NSTAGE);

        const float* Ab = As + buf * A_FLOATS + warpM * 32 * LDA_S;
        const float* Bb = Bs + buf * B_FLOATS + warpN * 64;
        #pragma unroll
        for (int ks = 0; ks < BLK_K / 8; ks++) {
            wmma::fragment<wmma::matrix_a, 16, 16, 8, wmma::precision::tf32, wmma::row_major> af[2];
            wmma::fragment<wmma::matrix_b, 16, 16, 8, wmma::precision::tf32, wmma::row_major> bf[4];
            #pragma unroll
            for (int mt = 0; mt < 2; mt++)
                wmma::load_matrix_sync(af[mt], Ab + mt * 16 * LDA_S + ks * 8, LDA_S);
            #pragma unroll
            for (int nt = 0; nt < 4; nt++)
                wmma::load_matrix_sync(bf[nt], Bb + ks * 8 * LDB_S + nt * 16, LDB_S);
            // operands pre-rounded to tf32: HW truncation is exact (RN overall)
            #pragma unroll
            for (int mt = 0; mt < 2; mt++)
                #pragma unroll
                for (int nt = 0; nt < 4; nt++)
                    wmma::mma_sync(acc[mt][nt], af[mt], bf[nt], acc[mt][nt]);
        }
    }

    __syncthreads();
    // epilogue: g_xl is padded, store unguarded
    #pragma unroll
    for (int mt = 0; mt < 2; mt++) {
        int row = m0 + warpM * 32 + mt * 16;
        #pragma unroll
        for (int nt = 0; nt < 4; nt++) {
            int col = n0 + warpN * 64 + nt * 16;
            wmma::store_matrix_sync(g_xl + (size_t)row * NDIM + col, acc[mt][nt],
                                    NDIM, wmma::mem_row_major);
        }
    }
}

// ---------------- per-node attention halves ----------------
__global__ void k_attn_halves(const float* __restrict__ att_src,
                              const float* __restrict__ att_dst) {
    int warp = (blockIdx.x * blockDim.x + threadIdx.x) >> 5;
    int lane = threadIdx.x & 31;
    if (warp >= NN * NH) return;
    int n = warp >> 2, h = warp & 3;
    const float4* row = (const float4*)(g_xl + (size_t)n * HC + h * OC);
    const float4* s4  = (const float4*)(att_src + h * OC);
    const float4* d4  = (const float4*)(att_dst + h * OC);
    float4 v = row[lane], s = s4[lane], d = d4[lane];
    float ss = v.x * s.x + v.y * s.y + v.z * s.z + v.w * s.w;
    float dd = v.x * d.x + v.y * d.y + v.z * d.z + v.w * d.w;
    #pragma unroll
    for (int o = 16; o; o >>= 1) {
        ss += __shfl_down_sync(0xFFFFFFFFu, ss, o);
        dd += __shfl_down_sync(0xFFFFFFFFu, dd, o);
    }
    if (lane == 0) { g_as[warp] = ss; g_ad[warp] = dd; }
}

__device__ __forceinline__ void atomicMaxFloat(float* addr, float value) {
    if (value >= 0.f) atomicMax((int*)addr, __float_as_int(value));
    else              atomicMin((unsigned int*)addr, __float_as_uint(value));
}
__device__ __forceinline__ float leaky(float a) { return a > 0.f ? a : 0.2f * a; }

// ---------------- segment max ----------------
__global__ void k_edge_max(const int* __restrict__ ei) {
    int i = blockIdx.x * blockDim.x + threadIdx.x;
    const int tot = (NE + NN) * NH;
    if (i >= tot) return;
    int e = i >> 2, h = i & 3;
    int src, dst;
    if (e < NE) { src = ei[e]; dst = ei[NE + e]; }
    else        { src = dst = e - NE; }
    float a = leaky(g_as[src * NH + h] + g_ad[dst * NH + h]);
    atomicMaxFloat(&g_amax[dst * NH + h], a);
}

// ---------------- segment sum ----------------
__global__ void k_edge_sum(const int* __restrict__ ei) {
    int i = blockIdx.x * blockDim.x + threadIdx.x;
    const int tot = (NE + NN) * NH;
    if (i >= tot) return;
    int e = i >> 2, h = i & 3;
    int src, dst;
    if (e < NE) { src = ei[e]; dst = ei[NE + e]; }
    else        { src = dst = e - NE; }
    float a = leaky(g_as[src * NH + h] + g_ad[dst * NH + h]);
    float ae = expf(a - g_amax[dst * NH + h]);
    atomicAdd(&g_den[dst * NH + h], ae);
}

// ---------------- weighted scatter: warp per edge ----------------
__global__ __launch_bounds__(256) void k_scatter(const int* __restrict__ ei,
                                                 float* __restrict__ out) {
    int e    = (blockIdx.x * blockDim.x + threadIdx.x) >> 5;
    int lane = threadIdx.x & 31;
    const int tot = NE + NN;
    if (e >= tot) return;
    int src, dst;
    if (e < NE) { src = __ldg(&ei[e]); dst = __ldg(&ei[NE + e]); }
    else        { src = dst = e - NE; }

    float w = 0.f;
    if (lane < 4) {
        float a  = leaky(g_as[src * NH + lane] + g_ad[dst * NH + lane]);
        float ae = expf(a - g_amax[dst * NH + lane]);
        w = ae / (g_den[dst * NH + lane] + 1e-16f);
    }
    float w0 = __shfl_sync(0xFFFFFFFFu, w, 0);
    float w1 = __shfl_sync(0xFFFFFFFFu, w, 1);
    float w2 = __shfl_sync(0xFFFFFFFFu, w, 2);
    float w3 = __shfl_sync(0xFFFFFFFFu, w, 3);

    const float4* xr = (const float4*)(g_xl + (size_t)src * HC);
    float4 x0 = __ldg(&xr[lane]);
    float4 x1 = __ldg(&xr[32 + lane]);
    float4 x2 = __ldg(&xr[64 + lane]);
    float4 x3 = __ldg(&xr[96 + lane]);

    float4 r;
    r.x = w0 * x0.x + w1 * x1.x + w2 * x2.x + w3 * x3.x;
    r.y = w0 * x0.y + w1 * x1.y + w2 * x2.y + w3 * x3.y;
    r.z = w0 * x0.z + w1 * x1.z + w2 * x2.z + w3 * x3.z;
    r.w = w0 * x0.w + w1 * x1.w + w2 * x2.w + w3 * x3.w;

    float* dp = out + (size_t)dst * OC + lane * 4;
    asm volatile("red.global.add.v4.f32 [%0], {%1, %2, %3, %4};"
                 :: "l"(dp), "f"(r.x), "f"(r.y), "f"(r.z), "f"(r.w)
                 : "memory");
}

// ---------------- finalize ----------------
__global__ void k_final(float* __restrict__ out, const float* __restrict__ bias) {
    int i = blockIdx.x * blockDim.x + threadIdx.x;
    if (i >= NN * OC) return;
    float v = out[i] * 0.25f + bias[i & (OC - 1)];
    out[i] = v > 0.f ? v : expm1f(v);
}

// ========================================================================
extern "C" void kernel_launch(void* const* d_in, const int* in_sizes, int n_in,
                              void* d_out, int out_size) {
    const float* x       = (const float*)d_in[0];
    const float* W       = (const float*)d_in[1];
    const float* att_src = (const float*)d_in[2];
    const float* att_dst = (const float*)d_in[3];
    const float* bias    = (const float*)d_in[4];
    const int*   ei      = (const int*)d_in[5];
    float* out = (float*)d_out;

    cudaFuncSetAttribute(k_gemm_tc, cudaFuncAttributeMaxDynamicSharedMemorySize,
                         GEMM_SMEM);

    k_init<<<(NN * OC + 255) / 256, 256>>>(out);

    // RN-round x and W to tf32 precision (makes HMMA truncation exact)
    const int cvt_tot = (NN * KDIM + KDIM * NDIM) / 4;
    k_cvt<<<(cvt_tot + 255) / 256, 256>>>(x, W);

    dim3 ggrid(NDIM / 128, (NN + 127) / 128);   // (4, 157)
    k_gemm_tc<<<ggrid, 256, GEMM_SMEM>>>();

    k_attn_halves<<<(NN * NH * 32 + 255) / 256, 256>>>(att_src, att_dst);

    const int etot4 = (NE + NN) * NH;
    k_edge_max<<<(etot4 + 255) / 256, 256>>>(ei);
    k_edge_sum<<<(etot4 + 255) / 256, 256>>>(ei);

    const int etot = NE + NN;
    k_scatter<<<(etot * 32 + 255) / 256, 256>>>(ei, out);

    k_final<<<(NN * OC + 255) / 256, 256>>>(out, bias);
}

// round 7
// speedup vs baseline: 1.0911x; 1.0911x over previous
#include <cuda_runtime.h>
#include <cuda_fp16.h>
#include <cfloat>
#include <math.h>
#include <cstdint>
#include <mma.h>

using namespace nvcuda;

// Problem constants
#define NN   20000
#define NE   320000
#define HC   512
#define NH   4
#define OC   128
#define KDIM 512
#define NDIM 512

// -------- scratch --------
__device__ __half g_xlh[(size_t)NN * HC];     // projected features, fp16
__device__ float  g_wc[(size_t)KDIM * NDIM];  // W, RN-rounded to tf32
__device__ float  g_as[NN * NH];              // per-node src attention half
__device__ float  g_ad[NN * NH];              // per-node dst attention half
__device__ float  g_den[NN * NH];             // softmax denominator per (dst,h)

// ---------------- init ----------------
__global__ void k_init(float* __restrict__ out) {
    int i = blockIdx.x * blockDim.x + threadIdx.x;
    if (i < NN * OC) out[i] = 0.f;
    if (i < NN * NH) g_den[i] = 0.f;
}

// ---------------- tf32 RN pre-conversion of W only (1 MB) ----------------
__device__ __forceinline__ float tf32rn(float f) {
    float r;
    asm("cvt.rna.tf32.f32 %0, %1;" : "=f"(r) : "f"(f));
    return r;
}
__global__ void k_cvt_w(const float* __restrict__ W) {
    int i = blockIdx.x * blockDim.x + threadIdx.x;
    if (i < KDIM * NDIM / 4) {
        float4 v = ((const float4*)W)[i];
        v.x = tf32rn(v.x); v.y = tf32rn(v.y); v.z = tf32rn(v.z); v.w = tf32rn(v.w);
        ((float4*)g_wc)[i] = v;
    }
}

// ---------------- GEMM + fused epilogue ----------------
// xl = x @ W (tf32 wmma, 128x128x32 tiles, 3-stage cp.async).
// Epilogue: per-row attention halves (head = blockIdx.x) + fp16 xl store.
#define BLK_K  32
#define LDA_S  36
#define LDB_S  136
#define A_FLOATS (128 * LDA_S)
#define B_FLOATS (BLK_K * LDB_S)
#define STAGE_FLOATS (A_FLOATS + B_FLOATS)
#define NSTAGE 3
#define GEMM_SMEM (NSTAGE * STAGE_FLOATS * 4)   // 107,520 B (also >= epilogue 67,584 B)
#define LDC 132

__device__ __forceinline__ uint32_t smem_u32(const void* p) {
    uint32_t a;
    asm("{ .reg .u64 t; cvta.to.shared.u64 t, %1; cvt.u32.u64 %0, t; }" : "=r"(a) : "l"(p));
    return a;
}

__global__ __launch_bounds__(256) void k_gemm_tc(const float* __restrict__ x,
                                                 const float* __restrict__ att_src,
                                                 const float* __restrict__ att_dst) {
    extern __shared__ float smem[];
    float* As = smem;                           // [NSTAGE][128][LDA_S]
    float* Bs = smem + NSTAGE * A_FLOATS;       // [NSTAGE][BLK_K][LDB_S]

    const int tid = threadIdx.x;
    const int warpId = tid >> 5;
    const int lane = tid & 31;
    const int warpM = warpId & 3;
    const int warpN = warpId >> 2;
    const int m0 = blockIdx.y * 128;
    const int n0 = blockIdx.x * 128;            // head h = blockIdx.x

    const uint32_t sA = smem_u32(As);
    const uint32_t sB = smem_u32(Bs);

    auto load_stage = [&](int kc, int buf) {
        const int k0 = kc * BLK_K;
        #pragma unroll
        for (int it = 0; it < 4; it++) {
            int id = tid + it * 256;
            int r = id >> 3, q = id & 7;
            int grow = m0 + r;
            const float* gp = x + (size_t)(grow < NN ? grow : 0) * KDIM + k0 + q * 4;
            int sz = (grow < NN) ? 16 : 0;
            uint32_t so = sA + (buf * A_FLOATS + r * LDA_S + q * 4) * 4;
            asm volatile("cp.async.cg.shared.global [%0], [%1], 16, %2;"
                         :: "r"(so), "l"(gp), "r"(sz));
        }
        #pragma unroll
        for (int it = 0; it < 4; it++) {
            int id = tid + it * 256;
            int r = id >> 5, q = id & 31;
            const float* gp = g_wc + (size_t)(k0 + r) * NDIM + n0 + q * 4;
            uint32_t so = sB + (buf * B_FLOATS + r * LDB_S + q * 4) * 4;
            asm volatile("cp.async.cg.shared.global [%0], [%1], 16;"
                         :: "r"(so), "l"(gp));
        }
        asm volatile("cp.async.commit_group;" ::: "memory");
    };

    wmma::fragment<wmma::accumulator, 16, 16, 8, float> acc[2][4];
    #pragma unroll
    for (int i = 0; i < 2; i++)
        #pragma unroll
        for (int j = 0; j < 4; j++) wmma::fill_fragment(acc[i][j], 0.f);

    load_stage(0, 0);
    load_stage(1, 1);

    const int NCHUNK = KDIM / BLK_K;   // 16
    for (int kc = 0; kc < NCHUNK; kc++) {
        const int buf = kc % NSTAGE;
        if (kc + 1 < NCHUNK)
            asm volatile("cp.async.wait_group 1;" ::: "memory");
        else
            asm volatile("cp.async.wait_group 0;" ::: "memory");
        __syncthreads();
        if (kc + 2 < NCHUNK) load_stage(kc + 2, (kc + 2) % NSTAGE);

        const float* Ab = As + buf * A_FLOATS + warpM * 32 * LDA_S;
        const float* Bb = Bs + buf * B_FLOATS + warpN * 64;
        #pragma unroll
        for (int ks = 0; ks < BLK_K / 8; ks++) {
            wmma::fragment<wmma::matrix_a, 16, 16, 8, wmma::precision::tf32, wmma::row_major> af[2];
            wmma::fragment<wmma::matrix_b, 16, 16, 8, wmma::precision::tf32, wmma::row_major> bf[4];
            #pragma unroll
            for (int mt = 0; mt < 2; mt++) {
                wmma::load_matrix_sync(af[mt], Ab + mt * 16 * LDA_S + ks * 8, LDA_S);
                #pragma unroll
                for (int e = 0; e < af[mt].num_elements; e++)
                    af[mt].x[e] = wmma::__float_to_tf32(af[mt].x[e]);  // A: RN in-loop
            }
            #pragma unroll
            for (int nt = 0; nt < 4; nt++)
                wmma::load_matrix_sync(bf[nt], Bb + ks * 8 * LDB_S + nt * 16, LDB_S);
            // B pre-rounded (g_wc): HW truncation exact
            #pragma unroll
            for (int mt = 0; mt < 2; mt++)
                #pragma unroll
                for (int nt = 0; nt < 4; nt++)
                    wmma::mma_sync(acc[mt][nt], af[mt], bf[nt], acc[mt][nt]);
        }
    }

    // -------- fused epilogue --------
    __syncthreads();
    float* Cs = smem;   // reuse pipeline smem: 128 x LDC fp32 = 67.6 KB
    #pragma unroll
    for (int mt = 0; mt < 2; mt++)
        #pragma unroll
        for (int nt = 0; nt < 4; nt++)
            wmma::store_matrix_sync(Cs + (warpM * 32 + mt * 16) * LDC + warpN * 64 + nt * 16,
                                    acc[mt][nt], LDC, wmma::mem_row_major);
    __syncthreads();

    const int h = blockIdx.x;
    float4 sv = *(const float4*)(att_src + h * OC + lane * 4);
    float4 dv = *(const float4*)(att_dst + h * OC + lane * 4);

    #pragma unroll
    for (int r = 0; r < 16; r++) {
        int lrow = warpId * 16 + r;
        int grow = m0 + lrow;
        float4 v = *(const float4*)(Cs + lrow * LDC + lane * 4);
        float ss = v.x * sv.x + v.y * sv.y + v.z * sv.z + v.w * sv.w;
        float dd = v.x * dv.x + v.y * dv.y + v.z * dv.z + v.w * dv.w;
        #pragma unroll
        for (int o = 16; o; o >>= 1) {
            ss += __shfl_xor_sync(0xFFFFFFFFu, ss, o);
            dd += __shfl_xor_sync(0xFFFFFFFFu, dd, o);
        }
        if (grow < NN) {
            union { uint2 u; __half2 hh[2]; } pk;
            pk.hh[0] = __floats2half2_rn(v.x, v.y);
            pk.hh[1] = __floats2half2_rn(v.z, v.w);
            *(uint2*)(g_xlh + (size_t)grow * HC + h * OC + lane * 4) = pk.u;
            if (lane == 0) {
                g_as[grow * NH + h] = ss;
                g_ad[grow * NH + h] = dd;
            }
        }
    }
}

__device__ __forceinline__ float leaky(float a) { return a > 0.f ? a : 0.2f * a; }

// ---------------- segment sum of exp(alpha) (no max shift) --------------
__global__ void k_edge_sum(const int* __restrict__ ei) {
    int i = blockIdx.x * blockDim.x + threadIdx.x;
    const int tot = (NE + NN) * NH;
    if (i >= tot) return;
    int e = i >> 2, h = i & 3;
    int src, dst;
    if (e < NE) { src = ei[e]; dst = ei[NE + e]; }
    else        { src = dst = e - NE; }
    float a = leaky(g_as[src * NH + h] + g_ad[dst * NH + h]);
    atomicAdd(&g_den[dst * NH + h], expf(a));
}

// ---------------- weighted scatter: warp per edge (fp16 gather) ---------
__global__ __launch_bounds__(256) void k_scatter(const int* __restrict__ ei,
                                                 float* __restrict__ out) {
    int e    = (blockIdx.x * blockDim.x + threadIdx.x) >> 5;
    int lane = threadIdx.x & 31;
    const int tot = NE + NN;
    if (e >= tot) return;
    int src, dst;
    if (e < NE) { src = __ldg(&ei[e]); dst = __ldg(&ei[NE + e]); }
    else        { src = dst = e - NE; }

    float w = 0.f;
    if (lane < 4) {
        float a  = leaky(g_as[src * NH + lane] + g_ad[dst * NH + lane]);
        w = expf(a) / (g_den[dst * NH + lane] + 1e-16f);
    }
    float w0 = __shfl_sync(0xFFFFFFFFu, w, 0);
    float w1 = __shfl_sync(0xFFFFFFFFu, w, 1);
    float w2 = __shfl_sync(0xFFFFFFFFu, w, 2);
    float w3 = __shfl_sync(0xFFFFFFFFu, w, 3);

    // per head h: lane covers cols [4*lane, 4*lane+4) => uint2 (4 halves)
    const uint2* xr = (const uint2*)(g_xlh + (size_t)src * HC);
    uint2 q0 = __ldg(&xr[lane]);
    uint2 q1 = __ldg(&xr[32 + lane]);
    uint2 q2 = __ldg(&xr[64 + lane]);
    uint2 q3 = __ldg(&xr[96 + lane]);

    float4 r;
    {
        float2 f0 = __half22float2(*(__half2*)&q0.x);
        float2 f1 = __half22float2(*(__half2*)&q0.y);
        r.x = w0 * f0.x; r.y = w0 * f0.y; r.z = w0 * f1.x; r.w = w0 * f1.y;
    }
    {
        float2 f0 = __half22float2(*(__half2*)&q1.x);
        float2 f1 = __half22float2(*(__half2*)&q1.y);
        r.x += w1 * f0.x; r.y += w1 * f0.y; r.z += w1 * f1.x; r.w += w1 * f1.y;
    }
    {
        float2 f0 = __half22float2(*(__half2*)&q2.x);
        float2 f1 = __half22float2(*(__half2*)&q2.y);
        r.x += w2 * f0.x; r.y += w2 * f0.y; r.z += w2 * f1.x; r.w += w2 * f1.y;
    }
    {
        float2 f0 = __half22float2(*(__half2*)&q3.x);
        float2 f1 = __half22float2(*(__half2*)&q3.y);
        r.x += w3 * f0.x; r.y += w3 * f0.y; r.z += w3 * f1.x; r.w += w3 * f1.y;
    }

    float* dp = out + (size_t)dst * OC + lane * 4;
    asm volatile("red.global.add.v4.f32 [%0], {%1, %2, %3, %4};"
                 :: "l"(dp), "f"(r.x), "f"(r.y), "f"(r.z), "f"(r.w)
                 : "memory");
}

// ---------------- finalize ----------------
__global__ void k_final(float* __restrict__ out, const float* __restrict__ bias) {
    int i = blockIdx.x * blockDim.x + threadIdx.x;
    if (i >= NN * OC) return;
    float v = out[i] * 0.25f + bias[i & (OC - 1)];
    out[i] = v > 0.f ? v : expm1f(v);
}

// ========================================================================
extern "C" void kernel_launch(void* const* d_in, const int* in_sizes, int n_in,
                              void* d_out, int out_size) {
    const float* x       = (const float*)d_in[0];
    const float* W       = (const float*)d_in[1];
    const float* att_src = (const float*)d_in[2];
    const float* att_dst = (const float*)d_in[3];
    const float* bias    = (const float*)d_in[4];
    const int*   ei      = (const int*)d_in[5];
    float* out = (float*)d_out;

    cudaFuncSetAttribute(k_gemm_tc, cudaFuncAttributeMaxDynamicSharedMemorySize,
                         GEMM_SMEM);

    k_init<<<(NN * OC + 255) / 256, 256>>>(out);
    k_cvt_w<<<(KDIM * NDIM / 4 + 255) / 256, 256>>>(W);

    dim3 ggrid(NDIM / 128, (NN + 127) / 128);   // (4, 157)
    k_gemm_tc<<<ggrid, 256, GEMM_SMEM>>>(x, att_src, att_dst);

    const int etot4 = (NE + NN) * NH;
    k_edge_sum<<<(etot4 + 255) / 256, 256>>>(ei);

    const int etot = NE + NN;
    k_scatter<<<(etot * 32 + 255) / 256, 256>>>(ei, out);

    k_final<<<(NN * OC + 255) / 256, 256>>>(out, bias);
}

// round 8
// speedup vs baseline: 2.2159x; 2.0310x over previous
#include <cuda_runtime.h>
#include <cuda_fp16.h>
#include <cfloat>
#include <math.h>
#include <cstdint>
#include <mma.h>

using namespace nvcuda;

// Problem constants
#define NN   20000
#define NE   320000
#define HC   512
#define NH   4
#define OC   128
#define KDIM 512
#define NDIM 512

// -------- scratch --------
__device__ __half g_xh[(size_t)NN * KDIM];    // x, fp16
__device__ __half g_wh[(size_t)KDIM * NDIM];  // W, fp16
__device__ __half g_xlh[(size_t)NN * HC];     // projected features, fp16
__device__ float  g_as[NN * NH];
__device__ float  g_ad[NN * NH];
__device__ float  g_den[NN * NH];

// ---------------- init ----------------
__global__ void k_init(float* __restrict__ out) {
    int i = blockIdx.x * blockDim.x + threadIdx.x;
    if (i < NN * OC) out[i] = 0.f;
    if (i < NN * NH) g_den[i] = 0.f;
}

// ---------------- fp16 pre-conversion of x and W ----------------
__global__ void k_cvt(const float* __restrict__ x, const float* __restrict__ W) {
    const int totx = NN * KDIM / 4;
    const int totw = KDIM * NDIM / 4;
    int i = blockIdx.x * blockDim.x + threadIdx.x;
    if (i < totx) {
        float4 v = ((const float4*)x)[i];
        union { uint2 u; __half2 h[2]; } pk;
        pk.h[0] = __floats2half2_rn(v.x, v.y);
        pk.h[1] = __floats2half2_rn(v.z, v.w);
        ((uint2*)g_xh)[i] = pk.u;
    } else if (i < totx + totw) {
        int j = i - totx;
        float4 v = ((const float4*)W)[j];
        union { uint2 u; __half2 h[2]; } pk;
        pk.h[0] = __floats2half2_rn(v.x, v.y);
        pk.h[1] = __floats2half2_rn(v.z, v.w);
        ((uint2*)g_wh)[j] = pk.u;
    }
}

// ---------------- GEMM (fp16 wmma 16x16x16) + fused epilogue -------------
// 128x128x64 tiles, 3-stage cp.async, fp32 accumulate.
// Epilogue: per-row attention halves (head = blockIdx.x) + fp16 xl store.
#define BLK_K  64
#define LDA_H  72      // 64 + 8 halves pad
#define LDB_H  136     // 128 + 8 halves pad
#define A_HALFS (128 * LDA_H)      // 9216
#define B_HALFS (BLK_K * LDB_H)    // 8704
#define STAGE_HALFS (A_HALFS + B_HALFS)
#define NSTAGE 3
#define GEMM_SMEM (NSTAGE * STAGE_HALFS * 2)   // 107,520 B
#define LDC 132

__device__ __forceinline__ uint32_t smem_u32(const void* p) {
    uint32_t a;
    asm("{ .reg .u64 t; cvta.to.shared.u64 t, %1; cvt.u32.u64 %0, t; }" : "=r"(a) : "l"(p));
    return a;
}

__global__ __launch_bounds__(256) void k_gemm_tc(const float* __restrict__ att_src,
                                                 const float* __restrict__ att_dst) {
    extern __shared__ __half smemh[];
    __half* As = smemh;                          // [NSTAGE][128][LDA_H]
    __half* Bs = smemh + NSTAGE * A_HALFS;       // [NSTAGE][BLK_K][LDB_H]

    const int tid = threadIdx.x;
    const int warpId = tid >> 5;
    const int lane = tid & 31;
    const int warpM = warpId & 3;
    const int warpN = warpId >> 2;
    const int m0 = blockIdx.y * 128;
    const int n0 = blockIdx.x * 128;             // head h = blockIdx.x

    const uint32_t sA = smem_u32(As);
    const uint32_t sB = smem_u32(Bs);

    auto load_stage = [&](int kc, int buf) {
        const int k0 = kc * BLK_K;
        // A: 128 rows x 64 halves (128 B/row) = 8 x 16B segments per row
        #pragma unroll
        for (int it = 0; it < 4; it++) {
            int id = tid + it * 256;
            int r = id >> 3, q = id & 7;
            int grow = m0 + r;
            const __half* gp = g_xh + (size_t)(grow < NN ? grow : 0) * KDIM + k0 + q * 8;
            int sz = (grow < NN) ? 16 : 0;
            uint32_t so = sA + (buf * A_HALFS + r * LDA_H + q * 8) * 2;
            asm volatile("cp.async.cg.shared.global [%0], [%1], 16, %2;"
                         :: "r"(so), "l"(gp), "r"(sz));
        }
        // B: 64 rows x 128 halves (256 B/row) = 16 x 16B segments per row
        #pragma unroll
        for (int it = 0; it < 4; it++) {
            int id = tid + it * 256;
            int r = id >> 4, q = id & 15;
            const __half* gp = g_wh + (size_t)(k0 + r) * NDIM + n0 + q * 8;
            uint32_t so = sB + (buf * B_HALFS + r * LDB_H + q * 8) * 2;
            asm volatile("cp.async.cg.shared.global [%0], [%1], 16;"
                         :: "r"(so), "l"(gp));
        }
        asm volatile("cp.async.commit_group;" ::: "memory");
    };

    wmma::fragment<wmma::accumulator, 16, 16, 16, float> acc[2][4];
    #pragma unroll
    for (int i = 0; i < 2; i++)
        #pragma unroll
        for (int j = 0; j < 4; j++) wmma::fill_fragment(acc[i][j], 0.f);

    load_stage(0, 0);
    load_stage(1, 1);

    const int NCHUNK = KDIM / BLK_K;   // 8
    for (int kc = 0; kc < NCHUNK; kc++) {
        const int buf = kc % NSTAGE;
        if (kc + 1 < NCHUNK)
            asm volatile("cp.async.wait_group 1;" ::: "memory");
        else
            asm volatile("cp.async.wait_group 0;" ::: "memory");
        __syncthreads();
        if (kc + 2 < NCHUNK) load_stage(kc + 2, (kc + 2) % NSTAGE);

        const __half* Ab = As + buf * A_HALFS + warpM * 32 * LDA_H;
        const __half* Bb = Bs + buf * B_HALFS + warpN * 64;
        #pragma unroll
        for (int ks = 0; ks < BLK_K / 16; ks++) {
            wmma::fragment<wmma::matrix_a, 16, 16, 16, __half, wmma::row_major> af[2];
            wmma::fragment<wmma::matrix_b, 16, 16, 16, __half, wmma::row_major> bf[4];
            #pragma unroll
            for (int mt = 0; mt < 2; mt++)
                wmma::load_matrix_sync(af[mt], Ab + mt * 16 * LDA_H + ks * 16, LDA_H);
            #pragma unroll
            for (int nt = 0; nt < 4; nt++)
                wmma::load_matrix_sync(bf[nt], Bb + ks * 16 * LDB_H + nt * 16, LDB_H);
            #pragma unroll
            for (int mt = 0; mt < 2; mt++)
                #pragma unroll
                for (int nt = 0; nt < 4; nt++)
                    wmma::mma_sync(acc[mt][nt], af[mt], bf[nt], acc[mt][nt]);
        }
    }

    // -------- fused epilogue --------
    __syncthreads();
    float* Cs = (float*)smemh;   // 128 x LDC fp32 = 67.6 KB (< GEMM_SMEM)
    #pragma unroll
    for (int mt = 0; mt < 2; mt++)
        #pragma unroll
        for (int nt = 0; nt < 4; nt++)
            wmma::store_matrix_sync(Cs + (warpM * 32 + mt * 16) * LDC + warpN * 64 + nt * 16,
                                    acc[mt][nt], LDC, wmma::mem_row_major);
    __syncthreads();

    const int h = blockIdx.x;
    float4 sv = *(const float4*)(att_src + h * OC + lane * 4);
    float4 dv = *(const float4*)(att_dst + h * OC + lane * 4);

    #pragma unroll
    for (int r = 0; r < 16; r++) {
        int lrow = warpId * 16 + r;
        int grow = m0 + lrow;
        float4 v = *(const float4*)(Cs + lrow * LDC + lane * 4);
        float ss = v.x * sv.x + v.y * sv.y + v.z * sv.z + v.w * sv.w;
        float dd = v.x * dv.x + v.y * dv.y + v.z * dv.z + v.w * dv.w;
        #pragma unroll
        for (int o = 16; o; o >>= 1) {
            ss += __shfl_xor_sync(0xFFFFFFFFu, ss, o);
            dd += __shfl_xor_sync(0xFFFFFFFFu, dd, o);
        }
        if (grow < NN) {
            union { uint2 u; __half2 hh[2]; } pk;
            pk.hh[0] = __floats2half2_rn(v.x, v.y);
            pk.hh[1] = __floats2half2_rn(v.z, v.w);
            *(uint2*)(g_xlh + (size_t)grow * HC + h * OC + lane * 4) = pk.u;
            if (lane == 0) {
                g_as[grow * NH + h] = ss;
                g_ad[grow * NH + h] = dd;
            }
        }
    }
}

__device__ __forceinline__ float leaky(float a) { return a > 0.f ? a : 0.2f * a; }

// ---------------- segment sum of exp(alpha) (no max shift) --------------
__global__ void k_edge_sum(const int* __restrict__ ei) {
    int i = blockIdx.x * blockDim.x + threadIdx.x;
    const int tot = (NE + NN) * NH;
    if (i >= tot) return;
    int e = i >> 2, h = i & 3;
    int src, dst;
    if (e < NE) { src = ei[e]; dst = ei[NE + e]; }
    else        { src = dst = e - NE; }
    float a = leaky(g_as[src * NH + h] + g_ad[dst * NH + h]);
    atomicAdd(&g_den[dst * NH + h], expf(a));
}

// ---------------- weighted scatter: warp per edge (fp16 gather) ---------
__global__ __launch_bounds__(256) void k_scatter(const int* __restrict__ ei,
                                                 float* __restrict__ out) {
    int e    = (blockIdx.x * blockDim.x + threadIdx.x) >> 5;
    int lane = threadIdx.x & 31;
    const int tot = NE + NN;
    if (e >= tot) return;
    int src, dst;
    if (e < NE) { src = __ldg(&ei[e]); dst = __ldg(&ei[NE + e]); }
    else        { src = dst = e - NE; }

    float w = 0.f;
    if (lane < 4) {
        float a  = leaky(g_as[src * NH + lane] + g_ad[dst * NH + lane]);
        w = expf(a) / (g_den[dst * NH + lane] + 1e-16f);
    }
    float w0 = __shfl_sync(0xFFFFFFFFu, w, 0);
    float w1 = __shfl_sync(0xFFFFFFFFu, w, 1);
    float w2 = __shfl_sync(0xFFFFFFFFu, w, 2);
    float w3 = __shfl_sync(0xFFFFFFFFu, w, 3);

    const uint2* xr = (const uint2*)(g_xlh + (size_t)src * HC);
    uint2 q0 = __ldg(&xr[lane]);
    uint2 q1 = __ldg(&xr[32 + lane]);
    uint2 q2 = __ldg(&xr[64 + lane]);
    uint2 q3 = __ldg(&xr[96 + lane]);

    float4 r;
    {
        float2 f0 = __half22float2(*(__half2*)&q0.x);
        float2 f1 = __half22float2(*(__half2*)&q0.y);
        r.x = w0 * f0.x; r.y = w0 * f0.y; r.z = w0 * f1.x; r.w = w0 * f1.y;
    }
    {
        float2 f0 = __half22float2(*(__half2*)&q1.x);
        float2 f1 = __half22float2(*(__half2*)&q1.y);
        r.x += w1 * f0.x; r.y += w1 * f0.y; r.z += w1 * f1.x; r.w += w1 * f1.y;
    }
    {
        float2 f0 = __half22float2(*(__half2*)&q2.x);
        float2 f1 = __half22float2(*(__half2*)&q2.y);
        r.x += w2 * f0.x; r.y += w2 * f0.y; r.z += w2 * f1.x; r.w += w2 * f1.y;
    }
    {
        float2 f0 = __half22float2(*(__half2*)&q3.x);
        float2 f1 = __half22float2(*(__half2*)&q3.y);
        r.x += w3 * f0.x; r.y += w3 * f0.y; r.z += w3 * f1.x; r.w += w3 * f1.y;
    }

    float* dp = out + (size_t)dst * OC + lane * 4;
    asm volatile("red.global.add.v4.f32 [%0], {%1, %2, %3, %4};"
                 :: "l"(dp), "f"(r.x), "f"(r.y), "f"(r.z), "f"(r.w)
                 : "memory");
}

// ---------------- finalize ----------------
__global__ void k_final(float* __restrict__ out, const float* __restrict__ bias) {
    int i = blockIdx.x * blockDim.x + threadIdx.x;
    if (i >= NN * OC) return;
    float v = out[i] * 0.25f + bias[i & (OC - 1)];
    out[i] = v > 0.f ? v : expm1f(v);
}

// ========================================================================
extern "C" void kernel_launch(void* const* d_in, const int* in_sizes, int n_in,
                              void* d_out, int out_size) {
    const float* x       = (const float*)d_in[0];
    const float* W       = (const float*)d_in[1];
    const float* att_src = (const float*)d_in[2];
    const float* att_dst = (const float*)d_in[3];
    const float* bias    = (const float*)d_in[4];
    const int*   ei      = (const int*)d_in[5];
    float* out = (float*)d_out;

    cudaFuncSetAttribute(k_gemm_tc, cudaFuncAttributeMaxDynamicSharedMemorySize,
                         GEMM_SMEM);

    k_init<<<(NN * OC + 255) / 256, 256>>>(out);

    const int cvt_tot = (NN * KDIM + KDIM * NDIM) / 4;
    k_cvt<<<(cvt_tot + 255) / 256, 256>>>(x, W);

    dim3 ggrid(NDIM / 128, (NN + 127) / 128);   // (4, 157)
    k_gemm_tc<<<ggrid, 256, GEMM_SMEM>>>(att_src, att_dst);

    const int etot4 = (NE + NN) * NH;
    k_edge_sum<<<(etot4 + 255) / 256, 256>>>(ei);

    const int etot = NE + NN;
    k_scatter<<<(etot * 32 + 255) / 256, 256>>>(ei, out);

    k_final<<<(NN * OC + 255) / 256, 256>>>(out, bias);
}